// round 6
// baseline (speedup 1.0000x reference)
#include <cuda_runtime.h>
#include <math.h>

#define NPTS 16384
#define DIM  64
#define NC   9
#define IT   128     // i-tile (points per block)
#define JT   64      // j-tile (rows per smem stage)
#define NB3  592     // k3 grid

// ---- device scratch (zero-initialized at load; k3 re-zeros per run) ----
__device__ float g_fn[NPTS * DIM];       // normalized features (valid points only)
__device__ float g_cf[NPTS * DIM];       // compacted class-sorted features
__device__ int   g_cls[NPTS];            // class 1..8 if valid member, else 0
__device__ int   g_cidx[NPTS];           // class-sorted point indices
__device__ int   g_ccls[NPTS + IT];      // class-sorted classes (padded with 0)
__device__ int   g_nvalid;
__device__ int   g_cnt[NC];
__device__ float g_sum[NC * DIM];        // per-class normalized-feature sums
__device__ float g_cross[NC * NC];       // ordered relu(dot) sums (2x unordered)
__device__ unsigned g_ticket;

// ---------------- K1: classify + normalize (1 warp / point) ----------------
__global__ void k1_classify(const int* __restrict__ labels,
                            const float* __restrict__ feats,
                            const float* __restrict__ scores) {
    int warp = (blockIdx.x * blockDim.x + threadIdx.x) >> 5;
    int lane = threadIdx.x & 31;
    if (warp >= NPTS) return;
    int p = warp;

    float x0 = feats[p * DIM + lane];
    float x1 = feats[p * DIM + 32 + lane];
    float ss = x0 * x0 + x1 * x1;
    #pragma unroll
    for (int o = 16; o > 0; o >>= 1) ss += __shfl_xor_sync(0xffffffffu, ss, o);
    float inv = 1.0f / fmaxf(sqrtf(ss), 1e-12f);

    float s = (lane < NC) ? scores[p * NC + lane] : -INFINITY;
    float mval = s; int midx = lane;
    #pragma unroll
    for (int o = 16; o > 0; o >>= 1) {
        float ov = __shfl_xor_sync(0xffffffffu, mval, o);
        int   oi = __shfl_xor_sync(0xffffffffu, midx, o);
        if (ov > mval || (ov == mval && oi < midx)) { mval = ov; midx = oi; }
    }
    float e = (lane < NC) ? expf(s - mval) : 0.f;
    #pragma unroll
    for (int o = 16; o > 0; o >>= 1) e += __shfl_xor_sync(0xffffffffu, e, o);
    float pmax = 1.0f / e;

    int lab = labels[p];
    int valid = (lab == midx) && (pmax >= 0.5f);
    int cls = (valid && lab >= 1) ? lab : 0;

    if (lane == 0) g_cls[p] = cls;
    if (cls > 0) {
        float f0 = x0 * inv, f1 = x1 * inv;
        g_fn[p * DIM + lane]      = f0;
        g_fn[p * DIM + 32 + lane] = f1;
        atomicAdd(&g_sum[cls * DIM + lane],      f0);
        atomicAdd(&g_sum[cls * DIM + 32 + lane], f1);
        if (lane == 0) atomicAdd(&g_cnt[cls], 1);
    }
}

// ------- K2: class-stable counting sort + compaction copy (1 block) --------
__global__ void k2_sort() {
    __shared__ int cstart[NC];
    __shared__ int running[NC];
    __shared__ int wcnt[NC][32];
    __shared__ int woff[NC][32];
    __shared__ int wtot[NC];
    int tid = threadIdx.x, lane = tid & 31, wid = tid >> 5;

    if (tid == 0) {
        int acc = 0;
        for (int c = 1; c < NC; c++) { cstart[c] = acc; acc += g_cnt[c]; }
        g_nvalid = acc;
    }
    if (tid < NC) running[tid] = 0;
    __syncthreads();

    unsigned lmask = (1u << lane) - 1u;
    for (int start = 0; start < NPTS; start += 1024) {
        int p = start + tid;
        int c = g_cls[p];
        int my_pre = 0;
        #pragma unroll
        for (int cc = 1; cc < NC; cc++) {
            unsigned bal = __ballot_sync(0xffffffffu, c == cc);
            if (c == cc) my_pre = __popc(bal & lmask);
            if (lane == 0) wcnt[cc][wid] = __popc(bal);
        }
        __syncthreads();
        if (wid < NC - 1) {
            int cc = wid + 1;
            int v = wcnt[cc][lane];
            int inc = v;
            #pragma unroll
            for (int o = 1; o < 32; o <<= 1) {
                int t2 = __shfl_up_sync(0xffffffffu, inc, o);
                if (lane >= o) inc += t2;
            }
            woff[cc][lane] = inc - v;
            if (lane == 31) wtot[cc] = inc;
        }
        __syncthreads();
        if (c > 0) {
            int pos = cstart[c] + running[c] + woff[c][wid] + my_pre;
            g_cidx[pos] = p;
            g_ccls[pos] = c;
        }
        __syncthreads();
        if (tid >= 1 && tid < NC) running[tid] += wtot[tid];
        __syncthreads();
    }

    // compaction copy: warp per row, padded to IT multiple with class 0
    int nv = g_nvalid;
    int nvpad = (nv + IT - 1) & ~(IT - 1);
    for (int pos = wid; pos < nvpad; pos += 32) {
        if (pos < nv) {
            int src = g_cidx[pos];
            g_cf[pos * DIM + lane]      = g_fn[src * DIM + lane];
            g_cf[pos * DIM + 32 + lane] = g_fn[src * DIM + 32 + lane];
        } else {
            if (lane == 0) g_ccls[pos] = 0;
        }
    }
}

// ------ K3: full-symmetric pairwise relu(dot); i-rows in registers --------
__global__ void __launch_bounds__(128) k3_rows(float* __restrict__ out) {
    __shared__ float4 Js[JT][16];
    __shared__ float  scross[NC * NC];
    __shared__ int    s_cs[NC], s_ce[NC];

    int tid = threadIdx.x;
    if (tid < NC * NC) scross[tid] = 0.f;
    if (tid == 0) {
        int acc = 0;
        for (int c = 1; c < NC; c++) { s_cs[c] = acc; acc += g_cnt[c]; s_ce[c] = acc; }
    }
    __syncthreads();

    int nv = g_nvalid;
    int nvpad = (nv + IT - 1) & ~(IT - 1);
    int nit = nvpad / IT;
    int njt = nvpad / JT;
    int njobs = nit * njt;

    const float4* cf4 = (const float4*)g_cf;

    for (int job = blockIdx.x; job < njobs; job += NB3) {
        int it = job / njt, jt = job - it * njt;
        int i = it * IT + tid;
        int ci = g_ccls[i];

        float4 row[16];
        #pragma unroll
        for (int c4 = 0; c4 < 16; c4++) row[c4] = cf4[i * 16 + c4];

        int jb = jt * JT;
        __syncthreads();   // protect Js from previous job's readers
        for (int q = tid; q < JT * 16; q += 128)
            Js[q >> 4][q & 15] = cf4[(jb + (q >> 4)) * 16 + (q & 15)];
        __syncthreads();

        if (ci > 0) {
            #pragma unroll
            for (int c = 1; c < NC; c++) {
                if (c == ci) continue;
                int rs = max(s_cs[c] - jb, 0);
                int re = min(s_ce[c] - jb, JT);
                if (rs >= re) continue;
                float rsum = 0.f;
                int j = rs;
                for (; j + 1 < re; j += 2) {
                    float d0x = 0.f, d0y = 0.f, d0z = 0.f, d0w = 0.f;
                    float d1x = 0.f, d1y = 0.f, d1z = 0.f, d1w = 0.f;
                    #pragma unroll
                    for (int c4 = 0; c4 < 16; c4++) {
                        float4 b0 = Js[j][c4];
                        float4 b1 = Js[j + 1][c4];
                        d0x += row[c4].x * b0.x; d0y += row[c4].y * b0.y;
                        d0z += row[c4].z * b0.z; d0w += row[c4].w * b0.w;
                        d1x += row[c4].x * b1.x; d1y += row[c4].y * b1.y;
                        d1z += row[c4].z * b1.z; d1w += row[c4].w * b1.w;
                    }
                    rsum += fmaxf((d0x + d0y) + (d0z + d0w), 0.f)
                          + fmaxf((d1x + d1y) + (d1z + d1w), 0.f);
                }
                if (j < re) {
                    float dx = 0.f, dy = 0.f, dz = 0.f, dw = 0.f;
                    #pragma unroll
                    for (int c4 = 0; c4 < 16; c4++) {
                        float4 b = Js[j][c4];
                        dx += row[c4].x * b.x; dy += row[c4].y * b.y;
                        dz += row[c4].z * b.z; dw += row[c4].w * b.w;
                    }
                    rsum += fmaxf((dx + dy) + (dz + dw), 0.f);
                }
                if (rsum > 0.f) {
                    int lo = min(ci, c), hi = max(ci, c);
                    atomicAdd(&scross[lo * NC + hi], rsum);
                }
            }
        }
    }
    __syncthreads();
    if (tid < NC * NC && scross[tid] != 0.f) atomicAdd(&g_cross[tid], scross[tid]);

    // ---- last-block finalize + re-zero for next graph replay ----
    __shared__ bool is_last;
    __threadfence();
    __syncthreads();
    if (tid == 0) is_last = (atomicAdd(&g_ticket, 1u) == NB3 - 1);
    __syncthreads();
    if (!is_last) return;
    __threadfence();

    __shared__ float red[128];
    float acc = 0.f;
    if (tid >= 1 && tid < NC) {
        float cnt = (float)g_cnt[tid];
        float quad = 0.f;
        #pragma unroll
        for (int d = 0; d < DIM; d++) {
            float v = g_sum[tid * DIM + d];
            quad += v * v;
        }
        float npairs = cnt * (cnt - 1.0f) * 0.5f;
        if (npairs > 0.f)
            acc += 1.0f - ((quad - cnt) * 0.5f) / npairs;
    }
    for (int idx = tid; idx < NC * NC; idx += 128) {
        int a = idx / NC, b = idx % NC;
        if (a >= 1 && b > a) {
            float den = (float)g_cnt[a] * (float)g_cnt[b];
            // g_cross holds ordered sums (both directions) = 2x unordered
            if (den > 0.f) acc += 0.5f * g_cross[a * NC + b] / den;
        }
    }
    red[tid] = acc;
    __syncthreads();
    #pragma unroll
    for (int o = 64; o > 0; o >>= 1) {
        if (tid < o) red[tid] += red[tid + o];
        __syncthreads();
    }
    if (tid == 0) out[0] = red[0];

    // re-zero accumulators so the next replay starts clean
    __syncthreads();
    if (tid < NC) g_cnt[tid] = 0;
    if (tid < NC * NC) g_cross[tid] = 0.f;
    for (int i = tid; i < NC * DIM; i += 128) g_sum[i] = 0.f;
    if (tid == 0) { g_nvalid = 0; g_ticket = 0; }
}

extern "C" void kernel_launch(void* const* d_in, const int* in_sizes, int n_in,
                              void* d_out, int out_size) {
    const int*   labels = nullptr;
    const float* feats  = nullptr;
    const float* scores = nullptr;
    for (int i = 0; i < n_in; i++) {
        if (in_sizes[i] == NPTS)            labels = (const int*)d_in[i];
        else if (in_sizes[i] == NPTS * DIM) feats  = (const float*)d_in[i];
        else if (in_sizes[i] == NPTS * NC)  scores = (const float*)d_in[i];
    }
    float* out = (float*)d_out;

    k1_classify<<<(NPTS * 32) / 256, 256>>>(labels, feats, scores);
    k2_sort<<<1, 1024>>>();
    k3_rows<<<NB3, 128>>>(out);
}

// round 7
// speedup vs baseline: 2.0315x; 2.0315x over previous
#include <cuda_runtime.h>
#include <math.h>

#define NPTS 16384
#define DIM  64
#define NC   9
#define IT   128     // i-tile for k3
#define JT   64      // j-tile rows staged in smem
#define NB3  592     // k3 grid
#define K1B  64      // k1 blocks (64 x 256 = 16384 threads)
#define K2B  512     // k2 blocks

// ---- device scratch (zero-init at load; k3 re-zeros per run) ----
__device__ float g_cf[NPTS * DIM];       // compacted class-grouped normalized feats
__device__ int   g_cls[NPTS];            // class 1..8 if valid member, else 0
__device__ int   g_ccls[NPTS + IT];      // compacted classes (padded with 0)
__device__ int   g_nvalid;
__device__ int   g_cnt[NC];
__device__ int   g_fill[NC];             // scatter cursors (start offsets)
__device__ float g_sum[NC * DIM];        // per-class normalized-feature sums
__device__ float g_cross[NC * NC];       // ordered relu(dot) sums (2x unordered)
__device__ unsigned g_t1, g_t3;

// ---- K1: classify (thread per point) + last-block prefix ----
__global__ void __launch_bounds__(256) k1_classify(const int* __restrict__ labels,
                                                   const float* __restrict__ scores) {
    __shared__ float ssc[256 * NC];
    __shared__ int   hc[NC];
    int tid = threadIdx.x;
    int p0 = blockIdx.x * 256;

    for (int q = tid; q < 256 * NC; q += 256) ssc[q] = scores[p0 * NC + q];
    if (tid < NC) hc[tid] = 0;
    __syncthreads();

    int p = p0 + tid;
    const float* sr = &ssc[tid * NC];   // stride 9 (odd) -> bank-conflict-free
    float mv = sr[0]; int mi = 0;
    #pragma unroll
    for (int c = 1; c < NC; c++) { float v = sr[c]; if (v > mv) { mv = v; mi = c; } }
    float e = 0.f;
    #pragma unroll
    for (int c = 0; c < NC; c++) e += expf(sr[c] - mv);
    float pmax = 1.0f / e;

    int lab = labels[p];
    int cls = (lab == mi && pmax >= 0.5f && lab >= 1) ? lab : 0;
    g_cls[p] = cls;

    if (cls > 0) atomicAdd(&hc[cls], 1);
    __syncthreads();
    if (tid >= 1 && tid < NC && hc[tid] > 0) atomicAdd(&g_cnt[tid], hc[tid]);

    // last block computes class prefix + padding
    __shared__ bool last;
    __threadfence();
    __syncthreads();
    if (tid == 0) last = (atomicAdd(&g_t1, 1u) == K1B - 1);
    __syncthreads();
    if (!last) return;
    __threadfence();

    __shared__ int s_nv;
    if (tid == 0) {
        int acc = 0;
        for (int c = 1; c < NC; c++) { g_fill[c] = acc; acc += g_cnt[c]; }
        g_nvalid = acc;
        s_nv = acc;
    }
    __syncthreads();
    int nv = s_nv;
    int nvpad = (nv + IT - 1) & ~(IT - 1);
    for (int i = nv + tid; i < nvpad; i += 256) g_ccls[i] = 0;
}

// ---- K2: parallel scatter — warp per point, valid points only ----
__global__ void __launch_bounds__(256) k2_scatter(const float* __restrict__ feats) {
    int gw = (blockIdx.x * blockDim.x + threadIdx.x) >> 5;
    int lane = threadIdx.x & 31;
    const int nw = (K2B * 256) >> 5;   // 4096 warps

    for (int p = gw; p < NPTS; p += nw) {
        int cls = g_cls[p];
        if (cls == 0) continue;

        float x0 = feats[p * DIM + lane];
        float x1 = feats[p * DIM + 32 + lane];
        float ss = x0 * x0 + x1 * x1;
        #pragma unroll
        for (int o = 16; o > 0; o >>= 1) ss += __shfl_xor_sync(0xffffffffu, ss, o);
        float inv = 1.0f / fmaxf(sqrtf(ss), 1e-12f);
        float f0 = x0 * inv, f1 = x1 * inv;

        int slot;
        if (lane == 0) slot = atomicAdd(&g_fill[cls], 1);
        slot = __shfl_sync(0xffffffffu, slot, 0);

        g_cf[slot * DIM + lane]      = f0;
        g_cf[slot * DIM + 32 + lane] = f1;
        if (lane == 0) g_ccls[slot] = cls;

        atomicAdd(&g_sum[cls * DIM + lane],      f0);
        atomicAdd(&g_sum[cls * DIM + 32 + lane], f1);
    }
}

// ---- K3: full-symmetric pairwise relu(dot); i-rows in registers ----
__global__ void __launch_bounds__(128, 4) k3_rows(float* __restrict__ out) {
    __shared__ float4 Js[JT][16];
    __shared__ float  scross[NC * NC];
    __shared__ int    s_cs[NC], s_ce[NC];

    int tid = threadIdx.x;
    if (tid < NC * NC) scross[tid] = 0.f;
    if (tid == 0) {
        int acc = 0;
        for (int c = 1; c < NC; c++) { s_cs[c] = acc; acc += g_cnt[c]; s_ce[c] = acc; }
    }
    __syncthreads();

    int nv = g_nvalid;
    int nvpad = (nv + IT - 1) & ~(IT - 1);
    int nit = nvpad / IT;
    int njt = nvpad / JT;
    int njobs = nit * njt;

    const float4* cf4 = (const float4*)g_cf;

    for (int job = blockIdx.x; job < njobs; job += NB3) {
        int it = job / njt, jt = job - it * njt;
        int i = it * IT + tid;
        int ci = g_ccls[i];

        float4 row[16];
        #pragma unroll
        for (int c4 = 0; c4 < 16; c4++) row[c4] = cf4[i * 16 + c4];

        int jb = jt * JT;
        __syncthreads();
        for (int q = tid; q < JT * 16; q += 128)
            Js[q >> 4][q & 15] = cf4[(jb + (q >> 4)) * 16 + (q & 15)];
        __syncthreads();

        if (ci > 0) {
            #pragma unroll
            for (int c = 1; c < NC; c++) {
                if (c == ci) continue;
                int rs = max(s_cs[c] - jb, 0);
                int re = min(s_ce[c] - jb, JT);
                if (rs >= re) continue;
                float rsum = 0.f;
                int j = rs;
                for (; j + 1 < re; j += 2) {
                    float d0x = 0.f, d0y = 0.f, d0z = 0.f, d0w = 0.f;
                    float d1x = 0.f, d1y = 0.f, d1z = 0.f, d1w = 0.f;
                    #pragma unroll
                    for (int c4 = 0; c4 < 16; c4++) {
                        float4 b0 = Js[j][c4];
                        float4 b1 = Js[j + 1][c4];
                        d0x += row[c4].x * b0.x; d0y += row[c4].y * b0.y;
                        d0z += row[c4].z * b0.z; d0w += row[c4].w * b0.w;
                        d1x += row[c4].x * b1.x; d1y += row[c4].y * b1.y;
                        d1z += row[c4].z * b1.z; d1w += row[c4].w * b1.w;
                    }
                    rsum += fmaxf((d0x + d0y) + (d0z + d0w), 0.f)
                          + fmaxf((d1x + d1y) + (d1z + d1w), 0.f);
                }
                if (j < re) {
                    float dx = 0.f, dy = 0.f, dz = 0.f, dw = 0.f;
                    #pragma unroll
                    for (int c4 = 0; c4 < 16; c4++) {
                        float4 b = Js[j][c4];
                        dx += row[c4].x * b.x; dy += row[c4].y * b.y;
                        dz += row[c4].z * b.z; dw += row[c4].w * b.w;
                    }
                    rsum += fmaxf((dx + dy) + (dz + dw), 0.f);
                }
                if (rsum > 0.f) {
                    int lo = min(ci, c), hi = max(ci, c);
                    atomicAdd(&scross[lo * NC + hi], rsum);
                }
            }
        }
    }
    __syncthreads();
    if (tid < NC * NC && scross[tid] != 0.f) atomicAdd(&g_cross[tid], scross[tid]);

    // ---- last-block finalize + re-zero for next graph replay ----
    __shared__ bool is_last;
    __threadfence();
    __syncthreads();
    if (tid == 0) is_last = (atomicAdd(&g_t3, 1u) == NB3 - 1);
    __syncthreads();
    if (!is_last) return;
    __threadfence();

    __shared__ float red[128];
    float acc = 0.f;
    if (tid >= 1 && tid < NC) {
        float cnt = (float)g_cnt[tid];
        float quad = 0.f;
        #pragma unroll
        for (int d = 0; d < DIM; d++) {
            float v = g_sum[tid * DIM + d];
            quad += v * v;
        }
        float npairs = cnt * (cnt - 1.0f) * 0.5f;
        if (npairs > 0.f)
            acc += 1.0f - ((quad - cnt) * 0.5f) / npairs;
    }
    for (int idx = tid; idx < NC * NC; idx += 128) {
        int a = idx / NC, b = idx % NC;
        if (a >= 1 && b > a) {
            float den = (float)g_cnt[a] * (float)g_cnt[b];
            // g_cross holds ordered (both-direction) sums = 2x unordered
            if (den > 0.f) acc += 0.5f * g_cross[a * NC + b] / den;
        }
    }
    red[tid] = acc;
    __syncthreads();
    #pragma unroll
    for (int o = 64; o > 0; o >>= 1) {
        if (tid < o) red[tid] += red[tid + o];
        __syncthreads();
    }
    if (tid == 0) out[0] = red[0];

    // re-zero for next replay
    __syncthreads();
    if (tid < NC) g_cnt[tid] = 0;
    if (tid < NC * NC) g_cross[tid] = 0.f;
    for (int i = tid; i < NC * DIM; i += 128) g_sum[i] = 0.f;
    if (tid == 0) { g_nvalid = 0; g_t1 = 0; g_t3 = 0; }
}

extern "C" void kernel_launch(void* const* d_in, const int* in_sizes, int n_in,
                              void* d_out, int out_size) {
    const int*   labels = nullptr;
    const float* feats  = nullptr;
    const float* scores = nullptr;
    for (int i = 0; i < n_in; i++) {
        if (in_sizes[i] == NPTS)            labels = (const int*)d_in[i];
        else if (in_sizes[i] == NPTS * DIM) feats  = (const float*)d_in[i];
        else if (in_sizes[i] == NPTS * NC)  scores = (const float*)d_in[i];
    }
    float* out = (float*)d_out;

    k1_classify<<<K1B, 256>>>(labels, scores);
    k2_scatter<<<K2B, 256>>>(feats);
    k3_rows<<<NB3, 128>>>(out);
}